// round 2
// baseline (speedup 1.0000x reference)
#include <cuda_runtime.h>
#include <cuda_bf16.h>

#define N_NODES 50000
#define N_FEAT  128
#define N_EDGES 600000
#define N_POWERS 3

// Flag: 1 if edge_index is genuinely int64 on device, 0 if int32.
// JAX with x64 disabled silently stores "int64" arrays as int32 — detect at runtime.
__device__ int g_idx_is64;

__global__ void detect_idx_kernel(const int* __restrict__ ei32)
{
    if (threadIdx.x == 0 && blockIdx.x == 0) {
        // If data is int64 (little-endian, values in [0, 50000)), every odd
        // 32-bit word is the zero high-half. If int32, odd words are random
        // indices -> probability all 128 are zero is ~0.
        int all_zero = 1;
#pragma unroll
        for (int k = 1; k < 256; k += 2) {
            all_zero &= (ei32[k] == 0);
        }
        g_idx_is64 = all_zero;
    }
}

// Warp-per-edge gather + tiny MLP.
// blockIdx.y = power p. Each lane owns 4 contiguous features -> one float4
// load per node row. Wa/ba/Wb/bb live in registers.
__global__ void __launch_bounds__(256, 8)
adj_learn_kernel(const float* __restrict__ x,
                 const void* __restrict__ edge_index_raw,
                 const float* __restrict__ Wa,
                 const float* __restrict__ ba,
                 const float* __restrict__ Wb,
                 const float* __restrict__ bb,
                 float* __restrict__ out)
{
    const int p    = blockIdx.y;
    const int lane = threadIdx.x & 31;
    const int warp = threadIdx.x >> 5;
    const int warps_per_block = blockDim.x >> 5;
    const int gwarp  = blockIdx.x * warps_per_block + warp;
    const int nwarps = gridDim.x * warps_per_block;

    const int is64 = g_idx_is64;

    // Per-lane slice of Wa[p]: features f0..f0+3, 3 hidden units each.
    const int f0 = lane * 4;
    const float* Wap = Wa + (size_t)p * (N_FEAT * 3);
    float w0[3], w1[3], w2[3], w3[3];
#pragma unroll
    for (int h = 0; h < 3; ++h) {
        w0[h] = Wap[(f0 + 0) * 3 + h];
        w1[h] = Wap[(f0 + 1) * 3 + h];
        w2[h] = Wap[(f0 + 2) * 3 + h];
        w3[h] = Wap[(f0 + 3) * 3 + h];
    }
    const float ba0 = ba[p * 3 + 0];
    const float ba1 = ba[p * 3 + 1];
    const float ba2 = ba[p * 3 + 2];
    const float wb0 = Wb[p * 3 + 0];
    const float wb1 = Wb[p * 3 + 1];
    const float wb2 = Wb[p * 3 + 2];
    const float bbv = bb[p];

    const int*       ei32 = (const int*)edge_index_raw;
    const long long* ei64 = (const long long*)edge_index_raw;
    const size_t src_base = (size_t)p * 2 * N_EDGES;
    const size_t dst_base = src_base + N_EDGES;
    float* outp = out + (size_t)p * N_EDGES;

    for (int e = gwarp; e < N_EDGES; e += nwarps) {
        int s = 0, d = 0;
        if (lane == 0) {
            if (is64) {
                s = (int)ei64[src_base + e];
                d = (int)ei64[dst_base + e];
            } else {
                s = ei32[src_base + e];
                d = ei32[dst_base + e];
            }
        }
        s = __shfl_sync(0xFFFFFFFFu, s, 0);
        d = __shfl_sync(0xFFFFFFFFu, d, 0);

        const float4 aj = *reinterpret_cast<const float4*>(x + (size_t)s * N_FEAT + f0);
        const float4 ai = *reinterpret_cast<const float4*>(x + (size_t)d * N_FEAT + f0);

        const float d0 = fabsf(aj.x - ai.x);
        const float d1 = fabsf(aj.y - ai.y);
        const float d2 = fabsf(aj.z - ai.z);
        const float d3 = fabsf(aj.w - ai.w);

        float acc0 = d0 * w0[0] + d1 * w1[0] + d2 * w2[0] + d3 * w3[0];
        float acc1 = d0 * w0[1] + d1 * w1[1] + d2 * w2[1] + d3 * w3[1];
        float acc2 = d0 * w0[2] + d1 * w1[2] + d2 * w2[2] + d3 * w3[2];

        // Warp butterfly reduce (3 values).
#pragma unroll
        for (int off = 16; off > 0; off >>= 1) {
            acc0 += __shfl_xor_sync(0xFFFFFFFFu, acc0, off);
            acc1 += __shfl_xor_sync(0xFFFFFFFFu, acc1, off);
            acc2 += __shfl_xor_sync(0xFFFFFFFFu, acc2, off);
        }

        if (lane == 0) {
            const float h0 = fmaxf(acc0 + ba0, 0.0f);
            const float h1 = fmaxf(acc1 + ba1, 0.0f);
            const float h2 = fmaxf(acc2 + ba2, 0.0f);
            const float z  = h0 * wb0 + h1 * wb1 + h2 * wb2 + bbv;
            outp[e] = 1.0f / (1.0f + __expf(-z));
        }
    }
}

extern "C" void kernel_launch(void* const* d_in, const int* in_sizes, int n_in,
                              void* d_out, int out_size)
{
    const float* x  = (const float*)d_in[0];
    const void*  ei = d_in[1];
    const float* Wa = (const float*)d_in[2];
    const float* ba = (const float*)d_in[3];
    const float* Wb = (const float*)d_in[4];
    const float* bb = (const float*)d_in[5];
    float* out = (float*)d_out;

    detect_idx_kernel<<<1, 32>>>((const int*)ei);

    dim3 grid(2048, N_POWERS, 1);
    dim3 block(256, 1, 1);
    adj_learn_kernel<<<grid, block>>>(x, ei, Wa, ba, Wb, bb, out);
}

// round 3
// speedup vs baseline: 1.3239x; 1.3239x over previous
#include <cuda_runtime.h>
#include <cuda_fp16.h>

#define N_NODES 50000
#define N_FEAT  128
#define N_EDGES 600000
#define N_POWERS 3

// fp16 staging copy of x (halves gather traffic + L1 wavefronts).
__device__ __half g_x16[(size_t)N_NODES * N_FEAT];

// 1 if edge_index is genuinely int64 on device, 0 if int32 (JAX x64-off).
__device__ int g_idx_is64;

__global__ void detect_idx_kernel(const int* __restrict__ ei32)
{
    if (threadIdx.x == 0 && blockIdx.x == 0) {
        int all_zero = 1;
#pragma unroll
        for (int k = 1; k < 256; k += 2) all_zero &= (ei32[k] == 0);
        g_idx_is64 = all_zero;
    }
}

// Convert x (fp32) -> g_x16 (fp16). 4 elements per thread.
__global__ void __launch_bounds__(256)
convert_x_kernel(const float* __restrict__ x)
{
    const int i = (blockIdx.x * blockDim.x + threadIdx.x) * 4;
    if (i < N_NODES * N_FEAT) {
        const float4 v = *reinterpret_cast<const float4*>(x + i);
        __half2 h0 = __floats2half2_rn(v.x, v.y);
        __half2 h1 = __floats2half2_rn(v.z, v.w);
        uint2 packed;
        packed.x = *reinterpret_cast<unsigned*>(&h0);
        packed.y = *reinterpret_cast<unsigned*>(&h1);
        *reinterpret_cast<uint2*>(&g_x16[i]) = packed;
    }
}

// 16 lanes per edge, 2 edges per warp. Each lane owns 8 features (uint4 of
// halves). Coalesced: one warp LDG.128 covers two full 256B rows (2 lines
// each). Reduction: 4 butterfly steps x 3 accs = 12 SHFL per 2 edges.
__global__ void __launch_bounds__(256, 8)
adj_learn_kernel(const void* __restrict__ edge_index_raw,
                 const float* __restrict__ Wa,
                 const float* __restrict__ ba,
                 const float* __restrict__ Wb,
                 const float* __restrict__ bb,
                 float* __restrict__ out)
{
    const int p    = blockIdx.y;
    const int lane = threadIdx.x & 31;
    const int l    = lane & 15;       // lane within edge-group
    const int g    = lane >> 4;       // which of the 2 edges in this warp
    const int warp = threadIdx.x >> 5;
    const int warps_per_block = blockDim.x >> 5;
    const int gwarp  = blockIdx.x * warps_per_block + warp;
    const int nwarps = gridDim.x * warps_per_block;

    const int is64 = g_idx_is64;

    // Per-lane weights: 8 features x 3 hidden.
    const int f0 = l * 8;
    const float* Wap = Wa + (size_t)p * (N_FEAT * 3);
    float w[8][3];
#pragma unroll
    for (int k = 0; k < 8; ++k)
#pragma unroll
        for (int h = 0; h < 3; ++h)
            w[k][h] = Wap[(f0 + k) * 3 + h];

    const float ba0 = ba[p * 3 + 0];
    const float ba1 = ba[p * 3 + 1];
    const float ba2 = ba[p * 3 + 2];
    const float wb0 = Wb[p * 3 + 0];
    const float wb1 = Wb[p * 3 + 1];
    const float wb2 = Wb[p * 3 + 2];
    const float bbv = bb[p];

    const int*       ei32 = (const int*)edge_index_raw;
    const long long* ei64 = (const long long*)edge_index_raw;
    const size_t src_base = (size_t)p * 2 * N_EDGES;
    const size_t dst_base = src_base + N_EDGES;
    float* outp = out + (size_t)p * N_EDGES;

    const int n_pairs = N_EDGES / 2;   // 300000

    for (int pi = gwarp; pi < n_pairs; pi += nwarps) {
        const int e = pi * 2 + g;

        // All 16 lanes of a group load the same index -> 1 wavefront, no SHFL.
        int s, d;
        if (is64) {
            s = (int)ei64[src_base + e];
            d = (int)ei64[dst_base + e];
        } else {
            s = ei32[src_base + e];
            d = ei32[dst_base + e];
        }

        const uint4 j4 = *reinterpret_cast<const uint4*>(&g_x16[(size_t)s * N_FEAT + f0]);
        const uint4 i4 = *reinterpret_cast<const uint4*>(&g_x16[(size_t)d * N_FEAT + f0]);

        const __half2* jh = reinterpret_cast<const __half2*>(&j4);
        const __half2* ih = reinterpret_cast<const __half2*>(&i4);

        float acc0 = 0.f, acc1 = 0.f, acc2 = 0.f;
#pragma unroll
        for (int k = 0; k < 4; ++k) {
            const __half2 dh = __habs2(__hsub2(jh[k], ih[k]));
            const float2 df = __half22float2(dh);
            acc0 = fmaf(df.x, w[2*k  ][0], acc0);
            acc1 = fmaf(df.x, w[2*k  ][1], acc1);
            acc2 = fmaf(df.x, w[2*k  ][2], acc2);
            acc0 = fmaf(df.y, w[2*k+1][0], acc0);
            acc1 = fmaf(df.y, w[2*k+1][1], acc1);
            acc2 = fmaf(df.y, w[2*k+1][2], acc2);
        }

        // Butterfly reduce within each 16-lane group.
#pragma unroll
        for (int off = 8; off > 0; off >>= 1) {
            acc0 += __shfl_xor_sync(0xFFFFFFFFu, acc0, off);
            acc1 += __shfl_xor_sync(0xFFFFFFFFu, acc1, off);
            acc2 += __shfl_xor_sync(0xFFFFFFFFu, acc2, off);
        }

        if (l == 0) {
            const float h0 = fmaxf(acc0 + ba0, 0.0f);
            const float h1 = fmaxf(acc1 + ba1, 0.0f);
            const float h2 = fmaxf(acc2 + ba2, 0.0f);
            const float z  = h0 * wb0 + h1 * wb1 + h2 * wb2 + bbv;
            outp[e] = 1.0f / (1.0f + __expf(-z));
        }
    }
}

extern "C" void kernel_launch(void* const* d_in, const int* in_sizes, int n_in,
                              void* d_out, int out_size)
{
    const float* x  = (const float*)d_in[0];
    const void*  ei = d_in[1];
    const float* Wa = (const float*)d_in[2];
    const float* ba = (const float*)d_in[3];
    const float* Wb = (const float*)d_in[4];
    const float* bb = (const float*)d_in[5];
    float* out = (float*)d_out;

    detect_idx_kernel<<<1, 32>>>((const int*)ei);

    convert_x_kernel<<<(N_NODES * N_FEAT / 4 + 255) / 256, 256>>>(x);

    dim3 grid(2048, N_POWERS, 1);
    dim3 block(256, 1, 1);
    adj_learn_kernel<<<grid, block>>>(ei, Wa, ba, Wb, bb, out);
}

// round 4
// speedup vs baseline: 2.4400x; 1.8431x over previous
#include <cuda_runtime.h>
#include <cuda_fp16.h>

#define N_NODES 50000
#define N_FEAT  128
#define N_EDGES 600000
#define N_POWERS 3

// fp16 staging copy of x (halves gather traffic + L1 wavefronts).
__device__ __half g_x16[(size_t)N_NODES * N_FEAT];

// 1 if edge_index is genuinely int64 on device, 0 if int32 (JAX x64-off).
__device__ int g_idx_is64;

// Convert x (fp32) -> g_x16 (fp16); block 0 thread 0 also sniffs the
// edge-index dtype (if int64 little-endian with values < 50000, every odd
// 32-bit word is zero; for int32 data that probability is ~0).
__global__ void __launch_bounds__(256)
convert_x_kernel(const float* __restrict__ x, const int* __restrict__ ei32)
{
    if (blockIdx.x == 0 && threadIdx.x == 0) {
        int all_zero = 1;
#pragma unroll
        for (int k = 1; k < 256; k += 2) all_zero &= (ei32[k] == 0);
        g_idx_is64 = all_zero;
    }
    const int i = (blockIdx.x * blockDim.x + threadIdx.x) * 4;
    if (i < N_NODES * N_FEAT) {
        const float4 v = *reinterpret_cast<const float4*>(x + i);
        __half2 h0 = __floats2half2_rn(v.x, v.y);
        __half2 h1 = __floats2half2_rn(v.z, v.w);
        uint2 packed;
        packed.x = *reinterpret_cast<unsigned*>(&h0);
        packed.y = *reinterpret_cast<unsigned*>(&h1);
        *reinterpret_cast<uint2*>(&g_x16[i]) = packed;
    }
}

// 8 lanes per edge, 4 edges per warp. Each lane owns 16 features (2x uint4 of
// halves per row). Layer-1 entirely in half2 (HFMA2); cross-lane reduce and
// layer-2 in fp32. Indices are software-pipelined one iteration ahead.
__global__ void __launch_bounds__(256, 4)
adj_learn_kernel(const void* __restrict__ edge_index_raw,
                 const float* __restrict__ Wa,
                 const float* __restrict__ ba,
                 const float* __restrict__ Wb,
                 const float* __restrict__ bb,
                 float* __restrict__ out)
{
    const int p    = blockIdx.y;
    const int lane = threadIdx.x & 31;
    const int l    = lane & 7;        // lane within edge-group (owns 16 feats)
    const int g    = lane >> 3;       // which of the 4 edges in this warp
    const int warp = threadIdx.x >> 5;
    const int warps_per_block = blockDim.x >> 5;
    const int gwarp  = blockIdx.x * warps_per_block + warp;
    const int nwarps = gridDim.x * warps_per_block;

    const int is64 = g_idx_is64;

    // Per-lane weights: 16 features x 3 hidden, packed as half2 feature-pairs.
    const int f0 = l * 16;
    const float* Wap = Wa + (size_t)p * (N_FEAT * 3);
    __half2 w2[3][8];
#pragma unroll
    for (int k = 0; k < 8; ++k) {
#pragma unroll
        for (int h = 0; h < 3; ++h) {
            w2[h][k] = __floats2half2_rn(Wap[(f0 + 2 * k) * 3 + h],
                                         Wap[(f0 + 2 * k + 1) * 3 + h]);
        }
    }
    const float ba0 = ba[p * 3 + 0];
    const float ba1 = ba[p * 3 + 1];
    const float ba2 = ba[p * 3 + 2];
    const float wb0 = Wb[p * 3 + 0];
    const float wb1 = Wb[p * 3 + 1];
    const float wb2 = Wb[p * 3 + 2];
    const float bbv = bb[p];

    const int*       ei32 = (const int*)edge_index_raw;
    const long long* ei64 = (const long long*)edge_index_raw;
    const size_t src_base = (size_t)p * 2 * N_EDGES;
    const size_t dst_base = src_base + N_EDGES;
    float* outp = out + (size_t)p * N_EDGES;

    const int n_grp = N_EDGES / 4;    // 150000 groups of 4 edges

    int pi = gwarp;
    int s = 0, d = 0;
    if (pi < n_grp) {
        const int e = pi * 4 + g;
        if (is64) { s = (int)ei64[src_base + e]; d = (int)ei64[dst_base + e]; }
        else      { s = ei32[src_base + e];      d = ei32[dst_base + e]; }
    }

    while (pi < n_grp) {
        // Prefetch next iteration's indices (breaks idx->gather dependence).
        const int pn = pi + nwarps;
        int sn = 0, dn = 0;
        if (pn < n_grp) {
            const int en = pn * 4 + g;
            if (is64) { sn = (int)ei64[src_base + en]; dn = (int)ei64[dst_base + en]; }
            else      { sn = ei32[src_base + en];      dn = ei32[dst_base + en]; }
        }

        // Gather both rows (2x uint4 = 32B of halves each).
        const uint4* rj = reinterpret_cast<const uint4*>(&g_x16[(size_t)s * N_FEAT + f0]);
        const uint4* ri = reinterpret_cast<const uint4*>(&g_x16[(size_t)d * N_FEAT + f0]);
        __half2 jv[8], iv[8];
        *reinterpret_cast<uint4*>(&jv[0]) = rj[0];
        *reinterpret_cast<uint4*>(&jv[4]) = rj[1];
        *reinterpret_cast<uint4*>(&iv[0]) = ri[0];
        *reinterpret_cast<uint4*>(&iv[4]) = ri[1];

        // Layer 1 in half2: acc_h[h] += |j - i| * w2[h].
        __half2 acc_h0 = __float2half2_rn(0.0f);
        __half2 acc_h1 = __float2half2_rn(0.0f);
        __half2 acc_h2 = __float2half2_rn(0.0f);
#pragma unroll
        for (int k = 0; k < 8; ++k) {
            const __half2 dh = __habs2(__hsub2(jv[k], iv[k]));
            acc_h0 = __hfma2(dh, w2[0][k], acc_h0);
            acc_h1 = __hfma2(dh, w2[1][k], acc_h1);
            acc_h2 = __hfma2(dh, w2[2][k], acc_h2);
        }

        // Convert per-lane partials to fp32, fold the two halves.
        const float2 f0v = __half22float2(acc_h0);
        const float2 f1v = __half22float2(acc_h1);
        const float2 f2v = __half22float2(acc_h2);
        float acc0 = f0v.x + f0v.y;
        float acc1 = f1v.x + f1v.y;
        float acc2 = f2v.x + f2v.y;

        // Butterfly reduce within the 8-lane group (fp32).
#pragma unroll
        for (int off = 4; off > 0; off >>= 1) {
            acc0 += __shfl_xor_sync(0xFFFFFFFFu, acc0, off);
            acc1 += __shfl_xor_sync(0xFFFFFFFFu, acc1, off);
            acc2 += __shfl_xor_sync(0xFFFFFFFFu, acc2, off);
        }

        if (l == 0) {
            const float h0 = fmaxf(acc0 + ba0, 0.0f);
            const float h1 = fmaxf(acc1 + ba1, 0.0f);
            const float h2 = fmaxf(acc2 + ba2, 0.0f);
            const float z  = h0 * wb0 + h1 * wb1 + h2 * wb2 + bbv;
            outp[pi * 4 + g] = 1.0f / (1.0f + __expf(-z));
        }

        s = sn; d = dn; pi = pn;
    }
}

extern "C" void kernel_launch(void* const* d_in, const int* in_sizes, int n_in,
                              void* d_out, int out_size)
{
    const float* x  = (const float*)d_in[0];
    const void*  ei = d_in[1];
    const float* Wa = (const float*)d_in[2];
    const float* ba = (const float*)d_in[3];
    const float* Wb = (const float*)d_in[4];
    const float* bb = (const float*)d_in[5];
    float* out = (float*)d_out;

    convert_x_kernel<<<(N_NODES * N_FEAT / 4 + 255) / 256, 256>>>(x, (const int*)ei);

    dim3 grid(512, N_POWERS, 1);
    dim3 block(256, 1, 1);
    adj_learn_kernel<<<grid, block>>>(ei, Wa, ba, Wb, bb, out);
}

// round 5
// speedup vs baseline: 2.6394x; 1.0817x over previous
#include <cuda_runtime.h>
#include <cuda_fp16.h>

#define N_NODES 50000
#define N_FEAT  128
#define N_EDGES 600000
#define N_POWERS 3

// fp16 staging copy of x (halves gather traffic + L1 wavefronts).
__device__ __half g_x16[(size_t)N_NODES * N_FEAT];

// 1 if edge_index is genuinely int64 on device, 0 if int32 (JAX x64-off).
__device__ int g_idx_is64;

// Convert x (fp32) -> g_x16 (fp16); block 0 thread 0 also sniffs the
// edge-index dtype (if int64 little-endian with values < 50000, every odd
// 32-bit word is zero; for int32 data that probability is ~0).
__global__ void __launch_bounds__(256)
convert_x_kernel(const float* __restrict__ x, const int* __restrict__ ei32)
{
    if (blockIdx.x == 0 && threadIdx.x == 0) {
        int all_zero = 1;
#pragma unroll
        for (int k = 1; k < 256; k += 2) all_zero &= (ei32[k] == 0);
        g_idx_is64 = all_zero;
    }
    const int i = (blockIdx.x * blockDim.x + threadIdx.x) * 4;
    if (i < N_NODES * N_FEAT) {
        const float4 v = *reinterpret_cast<const float4*>(x + i);
        __half2 h0 = __floats2half2_rn(v.x, v.y);
        __half2 h1 = __floats2half2_rn(v.z, v.w);
        uint2 packed;
        packed.x = *reinterpret_cast<unsigned*>(&h0);
        packed.y = *reinterpret_cast<unsigned*>(&h1);
        *reinterpret_cast<uint2*>(&g_x16[i]) = packed;
    }
}

// 8 lanes per edge, 4 edges per warp. Lane l owns two CONTIGUOUS 16B chunks
// per row: features [8l, 8l+8) and [64+8l, 64+8l+8) — so each warp-wide
// LDG.128 covers exactly one 128B line per edge-row (4 wavefronts/LDG,
// the fp16 data floor). Layer-1 in half2 (HFMA2); reduce + layer-2 in fp32.
__global__ void __launch_bounds__(256, 4)
adj_learn_kernel(const void* __restrict__ edge_index_raw,
                 const float* __restrict__ Wa,
                 const float* __restrict__ ba,
                 const float* __restrict__ Wb,
                 const float* __restrict__ bb,
                 float* __restrict__ out)
{
    const int p    = blockIdx.y;
    const int lane = threadIdx.x & 31;
    const int l    = lane & 7;        // lane within edge-group
    const int g    = lane >> 3;       // which of the 4 edges in this warp
    const int warp = threadIdx.x >> 5;
    const int warps_per_block = blockDim.x >> 5;
    const int gwarp  = blockIdx.x * warps_per_block + warp;
    const int nwarps = gridDim.x * warps_per_block;

    const int is64 = g_idx_is64;

    // Lane's two feature blocks (8 features each).
    const int fA = l * 8;         // bytes [16l, 16l+16) of the row
    const int fB = 64 + l * 8;    // bytes [128+16l, 128+16l+16)

    // Per-lane weights: half2 feature-pairs, k=0..3 -> block A, k=4..7 -> block B.
    const float* Wap = Wa + (size_t)p * (N_FEAT * 3);
    __half2 w2[3][8];
#pragma unroll
    for (int k = 0; k < 4; ++k) {
#pragma unroll
        for (int h = 0; h < 3; ++h) {
            w2[h][k]     = __floats2half2_rn(Wap[(fA + 2 * k) * 3 + h],
                                             Wap[(fA + 2 * k + 1) * 3 + h]);
            w2[h][k + 4] = __floats2half2_rn(Wap[(fB + 2 * k) * 3 + h],
                                             Wap[(fB + 2 * k + 1) * 3 + h]);
        }
    }
    const float ba0 = ba[p * 3 + 0];
    const float ba1 = ba[p * 3 + 1];
    const float ba2 = ba[p * 3 + 2];
    const float wb0 = Wb[p * 3 + 0];
    const float wb1 = Wb[p * 3 + 1];
    const float wb2 = Wb[p * 3 + 2];
    const float bbv = bb[p];

    const int*       ei32 = (const int*)edge_index_raw;
    const long long* ei64 = (const long long*)edge_index_raw;
    const size_t src_base = (size_t)p * 2 * N_EDGES;
    const size_t dst_base = src_base + N_EDGES;
    float* outp = out + (size_t)p * N_EDGES;

    const int n_grp = N_EDGES / 4;    // 150000 groups of 4 edges

    int pi = gwarp;
    int s = 0, d = 0;
    if (pi < n_grp) {
        const int e = pi * 4 + g;
        if (is64) { s = (int)ei64[src_base + e]; d = (int)ei64[dst_base + e]; }
        else      { s = ei32[src_base + e];      d = ei32[dst_base + e]; }
    }

    while (pi < n_grp) {
        // Prefetch next iteration's indices (breaks idx->gather dependence).
        const int pn = pi + nwarps;
        int sn = 0, dn = 0;
        if (pn < n_grp) {
            const int en = pn * 4 + g;
            if (is64) { sn = (int)ei64[src_base + en]; dn = (int)ei64[dst_base + en]; }
            else      { sn = ei32[src_base + en];      dn = ei32[dst_base + en]; }
        }

        const __half* rowj = &g_x16[(size_t)s * N_FEAT];
        const __half* rowi = &g_x16[(size_t)d * N_FEAT];

        __half2 jv[8], iv[8];
        *reinterpret_cast<uint4*>(&jv[0]) = *reinterpret_cast<const uint4*>(rowj + fA);
        *reinterpret_cast<uint4*>(&jv[4]) = *reinterpret_cast<const uint4*>(rowj + fB);
        *reinterpret_cast<uint4*>(&iv[0]) = *reinterpret_cast<const uint4*>(rowi + fA);
        *reinterpret_cast<uint4*>(&iv[4]) = *reinterpret_cast<const uint4*>(rowi + fB);

        // Layer 1 in half2: acc_h[h] += |j - i| * w2[h].
        __half2 acc_h0 = __float2half2_rn(0.0f);
        __half2 acc_h1 = __float2half2_rn(0.0f);
        __half2 acc_h2 = __float2half2_rn(0.0f);
#pragma unroll
        for (int k = 0; k < 8; ++k) {
            const __half2 dh = __habs2(__hsub2(jv[k], iv[k]));
            acc_h0 = __hfma2(dh, w2[0][k], acc_h0);
            acc_h1 = __hfma2(dh, w2[1][k], acc_h1);
            acc_h2 = __hfma2(dh, w2[2][k], acc_h2);
        }

        // Convert per-lane partials to fp32, fold the two halves.
        const float2 f0v = __half22float2(acc_h0);
        const float2 f1v = __half22float2(acc_h1);
        const float2 f2v = __half22float2(acc_h2);
        float acc0 = f0v.x + f0v.y;
        float acc1 = f1v.x + f1v.y;
        float acc2 = f2v.x + f2v.y;

        // Butterfly reduce within the 8-lane group (fp32).
#pragma unroll
        for (int off = 4; off > 0; off >>= 1) {
            acc0 += __shfl_xor_sync(0xFFFFFFFFu, acc0, off);
            acc1 += __shfl_xor_sync(0xFFFFFFFFu, acc1, off);
            acc2 += __shfl_xor_sync(0xFFFFFFFFu, acc2, off);
        }

        if (l == 0) {
            const float h0 = fmaxf(acc0 + ba0, 0.0f);
            const float h1 = fmaxf(acc1 + ba1, 0.0f);
            const float h2 = fmaxf(acc2 + ba2, 0.0f);
            const float z  = h0 * wb0 + h1 * wb1 + h2 * wb2 + bbv;
            outp[pi * 4 + g] = 1.0f / (1.0f + __expf(-z));
        }

        s = sn; d = dn; pi = pn;
    }
}

extern "C" void kernel_launch(void* const* d_in, const int* in_sizes, int n_in,
                              void* d_out, int out_size)
{
    const float* x  = (const float*)d_in[0];
    const void*  ei = d_in[1];
    const float* Wa = (const float*)d_in[2];
    const float* ba = (const float*)d_in[3];
    const float* Wb = (const float*)d_in[4];
    const float* bb = (const float*)d_in[5];
    float* out = (float*)d_out;

    convert_x_kernel<<<(N_NODES * N_FEAT / 4 + 255) / 256, 256>>>(x, (const int*)ei);

    dim3 grid(512, N_POWERS, 1);
    dim3 block(256, 1, 1);
    adj_learn_kernel<<<grid, block>>>(ei, Wa, ba, Wb, bb, out);
}

// round 6
// speedup vs baseline: 2.8333x; 1.0734x over previous
#include <cuda_runtime.h>
#include <cuda_fp16.h>

#define N_NODES 50000
#define N_FEAT  128
#define N_EDGES 600000
#define N_POWERS 3

// fp16 staging copy of x (halves gather traffic + L1 wavefronts).
__device__ __half g_x16[(size_t)N_NODES * N_FEAT];

// 1 if edge_index is genuinely int64 on device, 0 if int32 (JAX x64-off).
__device__ int g_idx_is64;

// Convert x (fp32) -> g_x16 (fp16); block 0 thread 0 also sniffs the
// edge-index dtype (int64 little-endian with values < 50000 -> every odd
// 32-bit word is zero; for int32 data that probability is ~0).
__global__ void __launch_bounds__(256)
convert_x_kernel(const float* __restrict__ x, const int* __restrict__ ei32)
{
    if (blockIdx.x == 0 && threadIdx.x == 0) {
        int all_zero = 1;
#pragma unroll
        for (int k = 1; k < 256; k += 2) all_zero &= (ei32[k] == 0);
        g_idx_is64 = all_zero;
    }
    const int i = (blockIdx.x * blockDim.x + threadIdx.x) * 4;
    if (i < N_NODES * N_FEAT) {
        const float4 v = *reinterpret_cast<const float4*>(x + i);
        __half2 h0 = __floats2half2_rn(v.x, v.y);
        __half2 h1 = __floats2half2_rn(v.z, v.w);
        uint2 packed;
        packed.x = *reinterpret_cast<unsigned*>(&h0);
        packed.y = *reinterpret_cast<unsigned*>(&h1);
        *reinterpret_cast<uint2*>(&g_x16[i]) = packed;
    }
}

// abs via sign-mask (LOP3 on alu pipe instead of HABS2 on fma pipe).
static __device__ __forceinline__ __half2 habs2_and(__half2 v) {
    unsigned u = *reinterpret_cast<unsigned*>(&v) & 0x7FFF7FFFu;
    return *reinterpret_cast<__half2*>(&u);
}

// 8 lanes per edge, 8 edges per warp-iteration (two 4-edge sub-groups A/B
// over adjacent edges). Lane l owns two contiguous 16B chunks per row:
// features [8l,8l+8) and [64+8l,64+8l+8) -> each warp LDG.128 covers exactly
// one 128B line per edge-row. All 8 gathers issue before any compute (MLP=8).
// Layer-1 in half2 (HFMA2); reduce + layer-2 in fp32.
__global__ void __launch_bounds__(256, 3)
adj_learn_kernel(const void* __restrict__ edge_index_raw,
                 const float* __restrict__ Wa,
                 const float* __restrict__ ba,
                 const float* __restrict__ Wb,
                 const float* __restrict__ bb,
                 float* __restrict__ out)
{
    const int p    = blockIdx.y;
    const int lane = threadIdx.x & 31;
    const int l    = lane & 7;        // lane within edge-group
    const int g    = lane >> 3;       // sub-group edge slot 0..3
    const int warp = threadIdx.x >> 5;
    const int warps_per_block = blockDim.x >> 5;
    const int gwarp  = blockIdx.x * warps_per_block + warp;
    const int nwarps = gridDim.x * warps_per_block;

    const int is64 = g_idx_is64;

    // Lane's two feature blocks (8 features each).
    const int fA = l * 8;
    const int fB = 64 + l * 8;

    // Per-lane weights: half2 feature-pairs, k=0..3 -> block A, k=4..7 -> block B.
    const float* Wap = Wa + (size_t)p * (N_FEAT * 3);
    __half2 w2[3][8];
#pragma unroll
    for (int k = 0; k < 4; ++k) {
#pragma unroll
        for (int h = 0; h < 3; ++h) {
            w2[h][k]     = __floats2half2_rn(Wap[(fA + 2 * k) * 3 + h],
                                             Wap[(fA + 2 * k + 1) * 3 + h]);
            w2[h][k + 4] = __floats2half2_rn(Wap[(fB + 2 * k) * 3 + h],
                                             Wap[(fB + 2 * k + 1) * 3 + h]);
        }
    }
    const float ba0 = ba[p * 3 + 0];
    const float ba1 = ba[p * 3 + 1];
    const float ba2 = ba[p * 3 + 2];
    const float wb0 = Wb[p * 3 + 0];
    const float wb1 = Wb[p * 3 + 1];
    const float wb2 = Wb[p * 3 + 2];
    const float bbv = bb[p];

    const int*       ei32 = (const int*)edge_index_raw;
    const long long* ei64 = (const long long*)edge_index_raw;
    const size_t src_base = (size_t)p * 2 * N_EDGES;
    const size_t dst_base = src_base + N_EDGES;
    float* outp = out + (size_t)p * N_EDGES;

    const int n_sup = N_EDGES / 8;    // 75000 super-groups of 8 edges

    int si = gwarp;
    int sA = 0, dA = 0, sB = 0, dB = 0;
    if (si < n_sup) {
        const int eA = si * 8 + g, eB = eA + 4;
        if (is64) {
            sA = (int)ei64[src_base + eA]; dA = (int)ei64[dst_base + eA];
            sB = (int)ei64[src_base + eB]; dB = (int)ei64[dst_base + eB];
        } else {
            sA = ei32[src_base + eA]; dA = ei32[dst_base + eA];
            sB = ei32[src_base + eB]; dB = ei32[dst_base + eB];
        }
    }

    while (si < n_sup) {
        // Prefetch next super-group's indices.
        const int sn = si + nwarps;
        int sAn = 0, dAn = 0, sBn = 0, dBn = 0;
        if (sn < n_sup) {
            const int eA = sn * 8 + g, eB = eA + 4;
            if (is64) {
                sAn = (int)ei64[src_base + eA]; dAn = (int)ei64[dst_base + eA];
                sBn = (int)ei64[src_base + eB]; dBn = (int)ei64[dst_base + eB];
            } else {
                sAn = ei32[src_base + eA]; dAn = ei32[dst_base + eA];
                sBn = ei32[src_base + eB]; dBn = ei32[dst_base + eB];
            }
        }

        // Issue all 8 gathers before any compute.
        const __half* rjA = &g_x16[(size_t)sA * N_FEAT];
        const __half* riA = &g_x16[(size_t)dA * N_FEAT];
        const __half* rjB = &g_x16[(size_t)sB * N_FEAT];
        const __half* riB = &g_x16[(size_t)dB * N_FEAT];

        __half2 jvA[8], ivA[8], jvB[8], ivB[8];
        *reinterpret_cast<uint4*>(&jvA[0]) = *reinterpret_cast<const uint4*>(rjA + fA);
        *reinterpret_cast<uint4*>(&jvA[4]) = *reinterpret_cast<const uint4*>(rjA + fB);
        *reinterpret_cast<uint4*>(&ivA[0]) = *reinterpret_cast<const uint4*>(riA + fA);
        *reinterpret_cast<uint4*>(&ivA[4]) = *reinterpret_cast<const uint4*>(riA + fB);
        *reinterpret_cast<uint4*>(&jvB[0]) = *reinterpret_cast<const uint4*>(rjB + fA);
        *reinterpret_cast<uint4*>(&jvB[4]) = *reinterpret_cast<const uint4*>(rjB + fB);
        *reinterpret_cast<uint4*>(&ivB[0]) = *reinterpret_cast<const uint4*>(riB + fA);
        *reinterpret_cast<uint4*>(&ivB[4]) = *reinterpret_cast<const uint4*>(riB + fB);

        __half2 a0A = __float2half2_rn(0.f), a1A = a0A, a2A = a0A;
        __half2 a0B = a0A, a1B = a0A, a2B = a0A;
#pragma unroll
        for (int k = 0; k < 8; ++k) {
            const __half2 dhA = habs2_and(__hsub2(jvA[k], ivA[k]));
            const __half2 dhB = habs2_and(__hsub2(jvB[k], ivB[k]));
            a0A = __hfma2(dhA, w2[0][k], a0A);
            a0B = __hfma2(dhB, w2[0][k], a0B);
            a1A = __hfma2(dhA, w2[1][k], a1A);
            a1B = __hfma2(dhB, w2[1][k], a1B);
            a2A = __hfma2(dhA, w2[2][k], a2A);
            a2B = __hfma2(dhB, w2[2][k], a2B);
        }

        // Fold halves to fp32.
        const float2 f0A = __half22float2(a0A), f1A = __half22float2(a1A), f2A = __half22float2(a2A);
        const float2 f0B = __half22float2(a0B), f1B = __half22float2(a1B), f2B = __half22float2(a2B);
        float x0A = f0A.x + f0A.y, x1A = f1A.x + f1A.y, x2A = f2A.x + f2A.y;
        float x0B = f0B.x + f0B.y, x1B = f1B.x + f1B.y, x2B = f2B.x + f2B.y;

        // Butterfly reduce within 8-lane groups (A and B interleaved for ILP).
#pragma unroll
        for (int off = 4; off > 0; off >>= 1) {
            x0A += __shfl_xor_sync(0xFFFFFFFFu, x0A, off);
            x0B += __shfl_xor_sync(0xFFFFFFFFu, x0B, off);
            x1A += __shfl_xor_sync(0xFFFFFFFFu, x1A, off);
            x1B += __shfl_xor_sync(0xFFFFFFFFu, x1B, off);
            x2A += __shfl_xor_sync(0xFFFFFFFFu, x2A, off);
            x2B += __shfl_xor_sync(0xFFFFFFFFu, x2B, off);
        }

        if (l == 0) {
            const float h0A = fmaxf(x0A + ba0, 0.f);
            const float h1A = fmaxf(x1A + ba1, 0.f);
            const float h2A = fmaxf(x2A + ba2, 0.f);
            const float zA  = h0A * wb0 + h1A * wb1 + h2A * wb2 + bbv;
            outp[si * 8 + g] = 1.0f / (1.0f + __expf(-zA));

            const float h0B = fmaxf(x0B + ba0, 0.f);
            const float h1B = fmaxf(x1B + ba1, 0.f);
            const float h2B = fmaxf(x2B + ba2, 0.f);
            const float zB  = h0B * wb0 + h1B * wb1 + h2B * wb2 + bbv;
            outp[si * 8 + 4 + g] = 1.0f / (1.0f + __expf(-zB));
        }

        si = sn;
        sA = sAn; dA = dAn; sB = sBn; dB = dBn;
    }
}

extern "C" void kernel_launch(void* const* d_in, const int* in_sizes, int n_in,
                              void* d_out, int out_size)
{
    const float* x  = (const float*)d_in[0];
    const void*  ei = d_in[1];
    const float* Wa = (const float*)d_in[2];
    const float* ba = (const float*)d_in[3];
    const float* Wb = (const float*)d_in[4];
    const float* bb = (const float*)d_in[5];
    float* out = (float*)d_out;

    convert_x_kernel<<<(N_NODES * N_FEAT / 4 + 255) / 256, 256>>>(x, (const int*)ei);

    dim3 grid(448, N_POWERS, 1);
    dim3 block(256, 1, 1);
    adj_learn_kernel<<<grid, block>>>(ei, Wa, ba, Wb, bb, out);
}